// round 14
// baseline (speedup 1.0000x reference)
#include <cuda_runtime.h>
#include <cstdint>

#define N1 50176
#define N2 12544
#define N3 3136

// ---------------- scratch (device globals; no runtime allocation) ----------------
__device__ float  g_xT[N1 * 24];        // x transposed to [n][c][b]
__device__ float  g_a1[N2 * 81];        // a = weight MLP(off1), [n][k][t]
__device__ float  g_a2[N2 * 81];
__device__ float  g_y1[N2 * 32 * 8];    // [n][o][b], pre-BN
__device__ float  g_y2[N2 * 32 * 8];
__device__ float  g_y3[N2 * 64 * 8];
__device__ double g_stats[256];         // sum1[32] sq1[32] sum2[32] sq2[32] sum3[64] sq3[64]
__device__ float  g_bnp[256];           // s1[32] t1[32] s2[32] t2[32] s3[64] t3[64]

// ---------------- small kernels ----------------
__global__ void zero_stats_kernel(double* st) { st[threadIdx.x] = 0.0; }

__global__ void mlp_kernel(const float* __restrict__ off1, const float* __restrict__ off2,
                           const float* __restrict__ Wh, const float* __restrict__ bh,
                           const float* __restrict__ Wo, const float* __restrict__ bo,
                           float* __restrict__ a1, float* __restrict__ a2)
{
    __shared__ float sWh[64], sbh[32], sWo[288], sbo[9];
    int tid = threadIdx.x;
    for (int i = tid; i < 64;  i += blockDim.x) sWh[i] = Wh[i];
    for (int i = tid; i < 32;  i += blockDim.x) sbh[i] = bh[i];
    for (int i = tid; i < 288; i += blockDim.x) sWo[i] = Wo[i];
    for (int i = tid; i < 9;   i += blockDim.x) sbo[i] = bo[i];
    __syncthreads();
    int g = blockIdx.x * blockDim.x + tid;
    const int TOT = N2 * 9;
    if (g >= 2 * TOT) return;
    const float* off; float* a; int idx;
    if (g < TOT) { off = off1; a = a1; idx = g; }
    else         { off = off2; a = a2; idx = g - TOT; }
    float x0 = off[idx * 2], x1 = off[idx * 2 + 1];
    float av[9];
#pragma unroll
    for (int t = 0; t < 9; ++t) av[t] = sbo[t];
#pragma unroll
    for (int j = 0; j < 32; ++j) {
        float h = fmaxf(fmaf(x0, sWh[j], fmaf(x1, sWh[32 + j], sbh[j])), 0.f);
#pragma unroll
        for (int t = 0; t < 9; ++t) av[t] = fmaf(h, sWo[j * 9 + t], av[t]);
    }
#pragma unroll
    for (int t = 0; t < 9; ++t) a[idx * 9 + t] = av[t];
}

__global__ void transpose_kernel(const float* __restrict__ x, float* __restrict__ xT)
{
    int tid = blockIdx.x * blockDim.x + threadIdx.x;
    if (tid >= 8 * 3 * N1) return;
    int n = tid % N1;
    int bc = tid / N1;
    int c = bc % 3;
    int b = bc / 3;
    xT[n * 24 + c * 8 + b] = x[tid];
}

__global__ void bnparams_kernel(const double* __restrict__ sum, const double* __restrict__ sq,
                                const float* __restrict__ g, const float* __restrict__ be,
                                float* __restrict__ s_out, float* __restrict__ t_out, int O)
{
    int o = threadIdx.x;
    if (o >= O) return;
    const double inv = 1.0 / (8.0 * (double)N2);
    double mean = sum[o] * inv;
    double var  = sq[o] * inv - mean * mean;
    float sc = g[o] * rsqrtf((float)var + 1e-5f);
    s_out[o] = sc;
    t_out[o] = be[o] - (float)mean * sc;
}

// ---------------- fused interp-conv ----------------
// in:  [Nin][C][8]  (previous layer output, pre-BN; BN+ReLU applied on gather if BNRELU)
// y:   [N2][O][8]   (this layer pre-BN output)
// Also accumulates per-channel sum / sumsq into gsum / gsq (doubles).
template<int C, int O, int NB, int NITER, bool BNRELU>
__global__ void __launch_bounds__(256) conv_kernel(
    const float* __restrict__ in, const int* __restrict__ nbr,
    const float* __restrict__ amat, const float* __restrict__ W,
    const float* __restrict__ bk,
    const float* __restrict__ bn_s, const float* __restrict__ bn_t,
    float* __restrict__ y, double* __restrict__ gsum, double* __restrict__ gsq)
{
    constexpr int C9 = C * 9;
    constexpr int CB = C * 8;
    constexpr int O4 = O / 4;
    static_assert(NB * 8 * O4 == 256, "thread mapping");

    extern __shared__ float sm[];
    float* Wt    = sm;                       // [C9][O]  (transposed weights)
    float* feats = Wt + C9 * O;              // [NB][9][CB]
    float* Ms    = feats + NB * 9 * CB;      // [NB][C9][8]
    float* as_   = Ms + NB * C9 * 8;         // [NB][81]
    float* ssum  = as_ + NB * 81;            // [O]
    float* ssq   = ssum + O;                 // [O]
    int*   nbr_s = (int*)(ssq + O);          // [NB][9]

    const int tid = threadIdx.x;

    // load W transposed: Wt[i*O + o] = W[o*C9 + i]
    for (int e = tid; e < C9 * O; e += 256) {
        int o = e % O, i = e / O;
        Wt[e] = W[o * C9 + i];
    }
    if (tid < O) { ssum[tid] = 0.f; ssq[tid] = 0.f; }

    // GEMM-phase role: (n-local, b, 4 consecutive o's)
    const int b  = tid & 7;
    const int rr = tid >> 3;
    const int og = rr % O4;
    const int nl = rr / O4;
    const int o0 = og * 4;

    float ps0 = 0.f, ps1 = 0.f, ps2 = 0.f, ps3 = 0.f;
    float pq0 = 0.f, pq1 = 0.f, pq2 = 0.f, pq3 = 0.f;
    const float bk0 = __ldg(bk + o0 + 0), bk1 = __ldg(bk + o0 + 1);
    const float bk2 = __ldg(bk + o0 + 2), bk3 = __ldg(bk + o0 + 3);

    const int nbase = blockIdx.x * (NB * NITER);
    for (int it = 0; it < NITER; ++it) {
        const int n0 = nbase + it * NB;
        if (tid < NB * 9) nbr_s[tid] = nbr[n0 * 9 + tid];
        for (int e = tid; e < NB * 81; e += 256) as_[e] = amat[n0 * 81 + e];
        __syncthreads();

        // gather K neighbor chunks, fusing previous layer's BN+ReLU
        for (int e = tid; e < NB * 9 * CB; e += 256) {
            int i  = e % CB;
            int rk = e / CB;
            int k  = rk % 9;
            int nn = rk / 9;
            int p  = nbr_s[nn * 9 + k];
            float v = in[p * CB + i];
            if (BNRELU) {
                int c = i >> 3;
                v = fmaxf(fmaf(v, __ldg(bn_s + c), __ldg(bn_t + c)), 0.f);
            }
            feats[e] = v;
        }
        __syncthreads();

        // M[b][c*9+t] = sum_k feats[k][c][b] * a[k][t]    (stored [i][8] so GEMM reads are bank-clean)
        for (int e = tid; e < NB * C9 * 8; e += 256) {
            int bb = e & 7;
            int r2 = e >> 3;
            int t  = r2 % 9;
            int r3 = r2 / 9;
            int c  = r3 % C;
            int nn = r3 / C;
            const float* fp = feats + nn * 9 * CB + c * 8 + bb;
            const float* ap = as_ + nn * 81 + t;
            float acc = 0.f;
#pragma unroll
            for (int k = 0; k < 9; ++k) acc = fmaf(fp[k * CB], ap[k * 9], acc);
            Ms[nn * (C9 * 8) + (c * 9 + t) * 8 + bb] = acc;
        }
        __syncthreads();

        // per-point GEMM: y[b][o0..o0+3] = bk + sum_i M[b][i] * Wt[i][o], packed f32x2 FMA
        {
            const float* Mp = Ms + nl * (C9 * 8) + b;
            const float* Wp = Wt + o0;
            unsigned long long a01, a23;
            asm("mov.b64 %0, {%1, %2};" : "=l"(a01) : "r"(__float_as_uint(bk0)), "r"(__float_as_uint(bk1)));
            asm("mov.b64 %0, {%1, %2};" : "=l"(a23) : "r"(__float_as_uint(bk2)), "r"(__float_as_uint(bk3)));
#pragma unroll 4
            for (int i = 0; i < C9; ++i) {
                float m = Mp[i * 8];
                ulonglong2 w = *reinterpret_cast<const ulonglong2*>(Wp + i * O);
                unsigned long long mm;
                asm("mov.b64 %0, {%1, %1};" : "=l"(mm) : "r"(__float_as_uint(m)));
                asm("fma.rn.f32x2 %0, %1, %2, %0;" : "+l"(a01) : "l"(mm), "l"(w.x));
                asm("fma.rn.f32x2 %0, %1, %2, %0;" : "+l"(a23) : "l"(mm), "l"(w.y));
            }
            unsigned u0, u1, u2, u3;
            asm("mov.b64 {%0, %1}, %2;" : "=r"(u0), "=r"(u1) : "l"(a01));
            asm("mov.b64 {%0, %1}, %2;" : "=r"(u2), "=r"(u3) : "l"(a23));
            float v0 = __uint_as_float(u0), v1 = __uint_as_float(u1);
            float v2 = __uint_as_float(u2), v3 = __uint_as_float(u3);
            float* yp = y + (n0 + nl) * (O * 8);
            yp[(o0 + 0) * 8 + b] = v0;
            yp[(o0 + 1) * 8 + b] = v1;
            yp[(o0 + 2) * 8 + b] = v2;
            yp[(o0 + 3) * 8 + b] = v3;
            ps0 += v0; pq0 += v0 * v0;
            ps1 += v1; pq1 += v1 * v1;
            ps2 += v2; pq2 += v2 * v2;
            ps3 += v3; pq3 += v3 * v3;
        }
        __syncthreads();
    }

    atomicAdd(&ssum[o0 + 0], ps0); atomicAdd(&ssq[o0 + 0], pq0);
    atomicAdd(&ssum[o0 + 1], ps1); atomicAdd(&ssq[o0 + 1], pq1);
    atomicAdd(&ssum[o0 + 2], ps2); atomicAdd(&ssq[o0 + 2], pq2);
    atomicAdd(&ssum[o0 + 3], ps3); atomicAdd(&ssq[o0 + 3], pq3);
    __syncthreads();
    if (tid < O) {
        atomicAdd(&gsum[tid], (double)ssum[tid]);
        atomicAdd(&gsq[tid],  (double)ssq[tid]);
    }
}

// ---------------- final pool: out[b][o][n3] = relu(max_k bn3(y3[p_k][o][b])) ----------------
__global__ void __launch_bounds__(512) pool_kernel(
    const float* __restrict__ y3, const int* __restrict__ pidx,
    const float* __restrict__ s, const float* __restrict__ t,
    float* __restrict__ out)
{
    __shared__ int sp[9];
    int n3 = blockIdx.x;
    int tid = threadIdx.x;
    if (tid < 9) sp[tid] = pidx[n3 * 9 + tid];
    __syncthreads();
    int o = tid >> 3, b = tid & 7;
    float sc = __ldg(s + o), sh = __ldg(t + o);
    float m = -3.4e38f;
#pragma unroll
    for (int k = 0; k < 9; ++k) {
        float v = y3[sp[k] * 512 + tid];
        m = fmaxf(m, fmaf(v, sc, sh));
    }
    out[(b * 64 + o) * N3 + n3] = fmaxf(m, 0.f);
}

// ---------------- launch ----------------
static constexpr int conv_smem_bytes(int C, int O, int NB) {
    return (C * 9 * O + NB * 9 * C * 8 + NB * C * 9 * 8 + NB * 81 + 2 * O) * 4 + NB * 9 * 4;
}

extern "C" void kernel_launch(void* const* d_in, const int* in_sizes, int n_in,
                              void* d_out, int out_size)
{
    const float* x    = (const float*)d_in[0];
    const int*   nbr1 = (const int*)  d_in[1];
    const float* off1 = (const float*)d_in[2];
    const int*   nbr2 = (const int*)  d_in[3];
    const float* off2 = (const float*)d_in[4];
    const int*   pidx = (const int*)  d_in[5];
    const float* Wh   = (const float*)d_in[6];
    const float* bh   = (const float*)d_in[7];
    const float* Wo   = (const float*)d_in[8];
    const float* bo   = (const float*)d_in[9];
    const float* W1   = (const float*)d_in[10];
    const float* b1   = (const float*)d_in[11];
    const float* W2   = (const float*)d_in[12];
    const float* b2   = (const float*)d_in[13];
    const float* W3   = (const float*)d_in[14];
    const float* b3   = (const float*)d_in[15];
    const float* g1   = (const float*)d_in[16];
    const float* be1  = (const float*)d_in[17];
    const float* g2   = (const float*)d_in[18];
    const float* be2  = (const float*)d_in[19];
    const float* g3   = (const float*)d_in[20];
    const float* be3  = (const float*)d_in[21];
    float* out = (float*)d_out;

    float *xT, *a1, *a2, *y1, *y2, *y3, *bnp;
    double* stats;
    cudaGetSymbolAddress((void**)&xT,    g_xT);
    cudaGetSymbolAddress((void**)&a1,    g_a1);
    cudaGetSymbolAddress((void**)&a2,    g_a2);
    cudaGetSymbolAddress((void**)&y1,    g_y1);
    cudaGetSymbolAddress((void**)&y2,    g_y2);
    cudaGetSymbolAddress((void**)&y3,    g_y3);
    cudaGetSymbolAddress((void**)&stats, g_stats);
    cudaGetSymbolAddress((void**)&bnp,   g_bnp);

    double* sum1 = stats +   0; double* sq1 = stats +  32;
    double* sum2 = stats +  64; double* sq2 = stats +  96;
    double* sum3 = stats + 128; double* sq3 = stats + 192;
    float* s1 = bnp +   0; float* t1 = bnp +  32;
    float* s2 = bnp +  64; float* t2 = bnp +  96;
    float* s3 = bnp + 128; float* t3 = bnp + 192;

    constexpr int SMEM_L1 = conv_smem_bytes(3, 32, 4);
    constexpr int SMEM_L2 = conv_smem_bytes(32, 32, 4);
    constexpr int SMEM_L3 = conv_smem_bytes(32, 64, 2);

    cudaFuncSetAttribute((const void*)conv_kernel<32, 32, 4, 4, true>,
                         cudaFuncAttributeMaxDynamicSharedMemorySize, SMEM_L2);
    cudaFuncSetAttribute((const void*)conv_kernel<32, 64, 2, 8, true>,
                         cudaFuncAttributeMaxDynamicSharedMemorySize, SMEM_L3);

    zero_stats_kernel<<<1, 256>>>(stats);
    mlp_kernel<<<(2 * N2 * 9) / 128, 128>>>(off1, off2, Wh, bh, Wo, bo, a1, a2);
    transpose_kernel<<<(8 * 3 * N1 + 255) / 256, 256>>>(x, xT);

    conv_kernel<3, 32, 4, 4, false><<<784, 256, SMEM_L1>>>(
        xT, nbr1, a1, W1, b1, nullptr, nullptr, y1, sum1, sq1);
    bnparams_kernel<<<1, 32>>>(sum1, sq1, g1, be1, s1, t1, 32);

    conv_kernel<32, 32, 4, 4, true><<<784, 256, SMEM_L2>>>(
        y1, nbr2, a2, W2, b2, s1, t1, y2, sum2, sq2);
    bnparams_kernel<<<1, 32>>>(sum2, sq2, g2, be2, s2, t2, 32);

    conv_kernel<32, 64, 2, 8, true><<<784, 256, SMEM_L3>>>(
        y2, nbr2, a2, W3, b3, s2, t2, y3, sum3, sq3);
    bnparams_kernel<<<1, 64>>>(sum3, sq3, g3, be3, s3, t3, 64);

    pool_kernel<<<N3, 512>>>(y3, pidx, s3, t3, out);
}

// round 15
// speedup vs baseline: 1.0037x; 1.0037x over previous
#include <cuda_runtime.h>
#include <cstdint>

#define N1 50176
#define N2 12544
#define N3 3136

// ---------------- scratch (device globals; no runtime allocation) ----------------
__device__ float  g_xT[N1 * 24];        // x transposed to [n][c][b]
__device__ float  g_a1[N2 * 81];        // a = weight MLP(off1), [n][k][t]
__device__ float  g_a2[N2 * 81];
__device__ float  g_y1[N2 * 32 * 8];    // [n][o][b], pre-BN
__device__ float  g_y2[N2 * 32 * 8];
__device__ float  g_y3[N2 * 64 * 8];
__device__ double g_stats[256];         // sum1[32] sq1[32] sum2[32] sq2[32] sum3[64] sq3[64]
__device__ float  g_bnp[256];           // s1[32] t1[32] s2[32] t2[32] s3[64] t3[64]

// ---------------- small kernels ----------------
__global__ void zero_stats_kernel(double* st) { st[threadIdx.x] = 0.0; }

__global__ void mlp_kernel(const float* __restrict__ off1, const float* __restrict__ off2,
                           const float* __restrict__ Wh, const float* __restrict__ bh,
                           const float* __restrict__ Wo, const float* __restrict__ bo,
                           float* __restrict__ a1, float* __restrict__ a2)
{
    __shared__ float sWh[64], sbh[32], sWo[288], sbo[9];
    int tid = threadIdx.x;
    for (int i = tid; i < 64;  i += blockDim.x) sWh[i] = Wh[i];
    for (int i = tid; i < 32;  i += blockDim.x) sbh[i] = bh[i];
    for (int i = tid; i < 288; i += blockDim.x) sWo[i] = Wo[i];
    for (int i = tid; i < 9;   i += blockDim.x) sbo[i] = bo[i];
    __syncthreads();
    int g = blockIdx.x * blockDim.x + tid;
    const int TOT = N2 * 9;
    if (g >= 2 * TOT) return;
    const float* off; float* a; int idx;
    if (g < TOT) { off = off1; a = a1; idx = g; }
    else         { off = off2; a = a2; idx = g - TOT; }
    float x0 = off[idx * 2], x1 = off[idx * 2 + 1];
    float av[9];
#pragma unroll
    for (int t = 0; t < 9; ++t) av[t] = sbo[t];
#pragma unroll
    for (int j = 0; j < 32; ++j) {
        float h = fmaxf(fmaf(x0, sWh[j], fmaf(x1, sWh[32 + j], sbh[j])), 0.f);
#pragma unroll
        for (int t = 0; t < 9; ++t) av[t] = fmaf(h, sWo[j * 9 + t], av[t]);
    }
#pragma unroll
    for (int t = 0; t < 9; ++t) a[idx * 9 + t] = av[t];
}

__global__ void transpose_kernel(const float* __restrict__ x, float* __restrict__ xT)
{
    int tid = blockIdx.x * blockDim.x + threadIdx.x;
    if (tid >= 8 * 3 * N1) return;
    int n = tid % N1;
    int bc = tid / N1;
    int c = bc % 3;
    int b = bc / 3;
    xT[n * 24 + c * 8 + b] = x[tid];
}

__global__ void bnparams_kernel(const double* __restrict__ sum, const double* __restrict__ sq,
                                const float* __restrict__ g, const float* __restrict__ be,
                                float* __restrict__ s_out, float* __restrict__ t_out, int O)
{
    int o = threadIdx.x;
    if (o >= O) return;
    const double inv = 1.0 / (8.0 * (double)N2);
    double mean = sum[o] * inv;
    double var  = sq[o] * inv - mean * mean;
    float sc = g[o] * rsqrtf((float)var + 1e-5f);
    s_out[o] = sc;
    t_out[o] = be[o] - (float)mean * sc;
}

// ---------------- fused interp-conv ----------------
// in:  [Nin][C][8]  (previous layer output, pre-BN; BN+ReLU applied on gather if BNRELU)
// y:   [N2][O][8]   (this layer pre-BN output)
// Also accumulates per-channel sum / sumsq into gsum / gsq (doubles).
template<int C, int O, int NB, int NITER, bool BNRELU>
__global__ void __launch_bounds__(256) conv_kernel(
    const float* __restrict__ in, const int* __restrict__ nbr,
    const float* __restrict__ amat, const float* __restrict__ W,
    const float* __restrict__ bk,
    const float* __restrict__ bn_s, const float* __restrict__ bn_t,
    float* __restrict__ y, double* __restrict__ gsum, double* __restrict__ gsq)
{
    constexpr int C9 = C * 9;
    constexpr int CB = C * 8;
    constexpr int O4 = O / 4;
    static_assert(NB * 8 * O4 == 256, "thread mapping");

    extern __shared__ float sm[];
    float* Wt    = sm;                       // [C9][O]  (transposed weights)
    float* feats = Wt + C9 * O;              // [NB][9][CB]
    float* Ms    = feats + NB * 9 * CB;      // [NB][C9][8]
    float* as_   = Ms + NB * C9 * 8;         // [NB][81]
    float* ssum  = as_ + NB * 81;            // [O]
    float* ssq   = ssum + O;                 // [O]
    int*   nbr_s = (int*)(ssq + O);          // [NB][9]

    const int tid = threadIdx.x;

    // load W transposed: Wt[i*O + o] = W[o*C9 + i]
    for (int e = tid; e < C9 * O; e += 256) {
        int o = e % O, i = e / O;
        Wt[e] = W[o * C9 + i];
    }
    if (tid < O) { ssum[tid] = 0.f; ssq[tid] = 0.f; }

    // GEMM-phase role: (n-local, b, 4 consecutive o's)
    const int b  = tid & 7;
    const int rr = tid >> 3;
    const int og = rr % O4;
    const int nl = rr / O4;
    const int o0 = og * 4;

    float ps0 = 0.f, ps1 = 0.f, ps2 = 0.f, ps3 = 0.f;
    float pq0 = 0.f, pq1 = 0.f, pq2 = 0.f, pq3 = 0.f;
    const float bk0 = __ldg(bk + o0 + 0), bk1 = __ldg(bk + o0 + 1);
    const float bk2 = __ldg(bk + o0 + 2), bk3 = __ldg(bk + o0 + 3);

    const int nbase = blockIdx.x * (NB * NITER);
    for (int it = 0; it < NITER; ++it) {
        const int n0 = nbase + it * NB;
        if (tid < NB * 9) nbr_s[tid] = nbr[n0 * 9 + tid];
        for (int e = tid; e < NB * 81; e += 256) as_[e] = amat[n0 * 81 + e];
        __syncthreads();

        // gather K neighbor chunks, fusing previous layer's BN+ReLU
        for (int e = tid; e < NB * 9 * CB; e += 256) {
            int i  = e % CB;
            int rk = e / CB;
            int k  = rk % 9;
            int nn = rk / 9;
            int p  = nbr_s[nn * 9 + k];
            float v = in[p * CB + i];
            if (BNRELU) {
                int c = i >> 3;
                v = fmaxf(fmaf(v, __ldg(bn_s + c), __ldg(bn_t + c)), 0.f);
            }
            feats[e] = v;
        }
        __syncthreads();

        // M[b][c*9+t] = sum_k feats[k][c][b] * a[k][t]    (stored [i][8] so GEMM reads are bank-clean)
        for (int e = tid; e < NB * C9 * 8; e += 256) {
            int bb = e & 7;
            int r2 = e >> 3;
            int t  = r2 % 9;
            int r3 = r2 / 9;
            int c  = r3 % C;
            int nn = r3 / C;
            const float* fp = feats + nn * 9 * CB + c * 8 + bb;
            const float* ap = as_ + nn * 81 + t;
            float acc = 0.f;
#pragma unroll
            for (int k = 0; k < 9; ++k) acc = fmaf(fp[k * CB], ap[k * 9], acc);
            Ms[nn * (C9 * 8) + (c * 9 + t) * 8 + bb] = acc;
        }
        __syncthreads();

        // per-point GEMM: y[b][o0..o0+3] = bk + sum_i M[b][i] * Wt[i][o], packed f32x2 FMA
        {
            const float* Mp = Ms + nl * (C9 * 8) + b;
            const float* Wp = Wt + o0;
            unsigned long long a01, a23;
            asm("mov.b64 %0, {%1, %2};" : "=l"(a01) : "r"(__float_as_uint(bk0)), "r"(__float_as_uint(bk1)));
            asm("mov.b64 %0, {%1, %2};" : "=l"(a23) : "r"(__float_as_uint(bk2)), "r"(__float_as_uint(bk3)));
#pragma unroll 4
            for (int i = 0; i < C9; ++i) {
                float m = Mp[i * 8];
                ulonglong2 w = *reinterpret_cast<const ulonglong2*>(Wp + i * O);
                unsigned long long mm;
                asm("mov.b64 %0, {%1, %1};" : "=l"(mm) : "r"(__float_as_uint(m)));
                asm("fma.rn.f32x2 %0, %1, %2, %0;" : "+l"(a01) : "l"(mm), "l"(w.x));
                asm("fma.rn.f32x2 %0, %1, %2, %0;" : "+l"(a23) : "l"(mm), "l"(w.y));
            }
            unsigned u0, u1, u2, u3;
            asm("mov.b64 {%0, %1}, %2;" : "=r"(u0), "=r"(u1) : "l"(a01));
            asm("mov.b64 {%0, %1}, %2;" : "=r"(u2), "=r"(u3) : "l"(a23));
            float v0 = __uint_as_float(u0), v1 = __uint_as_float(u1);
            float v2 = __uint_as_float(u2), v3 = __uint_as_float(u3);
            float* yp = y + (n0 + nl) * (O * 8);
            yp[(o0 + 0) * 8 + b] = v0;
            yp[(o0 + 1) * 8 + b] = v1;
            yp[(o0 + 2) * 8 + b] = v2;
            yp[(o0 + 3) * 8 + b] = v3;
            ps0 += v0; pq0 += v0 * v0;
            ps1 += v1; pq1 += v1 * v1;
            ps2 += v2; pq2 += v2 * v2;
            ps3 += v3; pq3 += v3 * v3;
        }
        __syncthreads();
    }

    atomicAdd(&ssum[o0 + 0], ps0); atomicAdd(&ssq[o0 + 0], pq0);
    atomicAdd(&ssum[o0 + 1], ps1); atomicAdd(&ssq[o0 + 1], pq1);
    atomicAdd(&ssum[o0 + 2], ps2); atomicAdd(&ssq[o0 + 2], pq2);
    atomicAdd(&ssum[o0 + 3], ps3); atomicAdd(&ssq[o0 + 3], pq3);
    __syncthreads();
    if (tid < O) {
        atomicAdd(&gsum[tid], (double)ssum[tid]);
        atomicAdd(&gsq[tid],  (double)ssq[tid]);
    }
}

// ---------------- final pool: out[b][o][n3] = relu(max_k bn3(y3[p_k][o][b])) ----------------
__global__ void __launch_bounds__(512) pool_kernel(
    const float* __restrict__ y3, const int* __restrict__ pidx,
    const float* __restrict__ s, const float* __restrict__ t,
    float* __restrict__ out)
{
    __shared__ int sp[9];
    int n3 = blockIdx.x;
    int tid = threadIdx.x;
    if (tid < 9) sp[tid] = pidx[n3 * 9 + tid];
    __syncthreads();
    int o = tid >> 3, b = tid & 7;
    float sc = __ldg(s + o), sh = __ldg(t + o);
    float m = -3.4e38f;
#pragma unroll
    for (int k = 0; k < 9; ++k) {
        float v = y3[sp[k] * 512 + tid];
        m = fmaxf(m, fmaf(v, sc, sh));
    }
    out[(b * 64 + o) * N3 + n3] = fmaxf(m, 0.f);
}

// ---------------- launch ----------------
static constexpr int conv_smem_bytes(int C, int O, int NB) {
    return (C * 9 * O + NB * 9 * C * 8 + NB * C * 9 * 8 + NB * 81 + 2 * O) * 4 + NB * 9 * 4;
}

extern "C" void kernel_launch(void* const* d_in, const int* in_sizes, int n_in,
                              void* d_out, int out_size)
{
    const float* x    = (const float*)d_in[0];
    const int*   nbr1 = (const int*)  d_in[1];
    const float* off1 = (const float*)d_in[2];
    const int*   nbr2 = (const int*)  d_in[3];
    const float* off2 = (const float*)d_in[4];
    const int*   pidx = (const int*)  d_in[5];
    const float* Wh   = (const float*)d_in[6];
    const float* bh   = (const float*)d_in[7];
    const float* Wo   = (const float*)d_in[8];
    const float* bo   = (const float*)d_in[9];
    const float* W1   = (const float*)d_in[10];
    const float* b1   = (const float*)d_in[11];
    const float* W2   = (const float*)d_in[12];
    const float* b2   = (const float*)d_in[13];
    const float* W3   = (const float*)d_in[14];
    const float* b3   = (const float*)d_in[15];
    const float* g1   = (const float*)d_in[16];
    const float* be1  = (const float*)d_in[17];
    const float* g2   = (const float*)d_in[18];
    const float* be2  = (const float*)d_in[19];
    const float* g3   = (const float*)d_in[20];
    const float* be3  = (const float*)d_in[21];
    float* out = (float*)d_out;

    float *xT, *a1, *a2, *y1, *y2, *y3, *bnp;
    double* stats;
    cudaGetSymbolAddress((void**)&xT,    g_xT);
    cudaGetSymbolAddress((void**)&a1,    g_a1);
    cudaGetSymbolAddress((void**)&a2,    g_a2);
    cudaGetSymbolAddress((void**)&y1,    g_y1);
    cudaGetSymbolAddress((void**)&y2,    g_y2);
    cudaGetSymbolAddress((void**)&y3,    g_y3);
    cudaGetSymbolAddress((void**)&stats, g_stats);
    cudaGetSymbolAddress((void**)&bnp,   g_bnp);

    double* sum1 = stats +   0; double* sq1 = stats +  32;
    double* sum2 = stats +  64; double* sq2 = stats +  96;
    double* sum3 = stats + 128; double* sq3 = stats + 192;
    float* s1 = bnp +   0; float* t1 = bnp +  32;
    float* s2 = bnp +  64; float* t2 = bnp +  96;
    float* s3 = bnp + 128; float* t3 = bnp + 192;

    constexpr int SMEM_L1 = conv_smem_bytes(3, 32, 4);
    constexpr int SMEM_L2 = conv_smem_bytes(32, 32, 4);
    constexpr int SMEM_L3 = conv_smem_bytes(32, 64, 2);

    cudaFuncSetAttribute((const void*)conv_kernel<32, 32, 4, 4, true>,
                         cudaFuncAttributeMaxDynamicSharedMemorySize, SMEM_L2);
    cudaFuncSetAttribute((const void*)conv_kernel<32, 64, 2, 8, true>,
                         cudaFuncAttributeMaxDynamicSharedMemorySize, SMEM_L3);

    zero_stats_kernel<<<1, 256>>>(stats);
    mlp_kernel<<<(2 * N2 * 9) / 128, 128>>>(off1, off2, Wh, bh, Wo, bo, a1, a2);
    transpose_kernel<<<(8 * 3 * N1 + 255) / 256, 256>>>(x, xT);

    conv_kernel<3, 32, 4, 4, false><<<784, 256, SMEM_L1>>>(
        xT, nbr1, a1, W1, b1, nullptr, nullptr, y1, sum1, sq1);
    bnparams_kernel<<<1, 32>>>(sum1, sq1, g1, be1, s1, t1, 32);

    conv_kernel<32, 32, 4, 4, true><<<784, 256, SMEM_L2>>>(
        y1, nbr2, a2, W2, b2, s1, t1, y2, sum2, sq2);
    bnparams_kernel<<<1, 32>>>(sum2, sq2, g2, be2, s2, t2, 32);

    conv_kernel<32, 64, 2, 8, true><<<784, 256, SMEM_L3>>>(
        y2, nbr2, a2, W3, b3, s2, t2, y3, sum3, sq3);
    bnparams_kernel<<<1, 64>>>(sum3, sq3, g3, be3, s3, t3, 64);

    pool_kernel<<<N3, 512>>>(y3, pidx, s3, t3, out);
}